// round 8
// baseline (speedup 1.0000x reference)
#include <cuda_runtime.h>
#include <math.h>

#define N_TOT  8192
#define NF     8
#define HID    64
#define TILE   16
#define NTHR   128
#define NBLK   (N_TOT / TILE)   // 512
#define PIT    20               // smem row pitch in floats (80B: 16B-aligned rows)

typedef unsigned long long ull;

__device__ __forceinline__ float sigm(float x) {
    return 1.0f / (1.0f + __expf(-x));
}

// Accurate tanh (only where it feeds an output directly).
__device__ __forceinline__ float tanh_acc(float x) {
    float ax = fabsf(x);
    if (ax < 0.0625f) {
        float x2 = x * x;
        return x * (1.0f + x2 * (-0.33333333f + x2 * 0.13333334f));
    }
    float e = __expf(-2.0f * ax);
    float r = (1.0f - e) / (1.0f + e);
    return (x < 0.0f) ? -r : r;
}

// HW tanh approximation (MUFU.TANH) for hidden layers.
__device__ __forceinline__ float tanha(float x) {
    float r;
    asm("tanh.approx.f32 %0, %1;" : "=f"(r) : "f"(x));
    return r;
}

// Packed dual-lane FMA (sm_103a FFMA2; ptxas never emits from C++).
__device__ __forceinline__ ull fma2(ull a, ull b, ull c) {
    ull d;
    asm("fma.rn.f32x2 %0, %1, %2, %3;" : "=l"(d) : "l"(a), "l"(b), "l"(c));
    return d;
}
__device__ __forceinline__ float2 unpack2(ull v) {
    float2 r;
    asm("mov.b64 {%0, %1}, %2;" : "=f"(r.x), "=f"(r.y) : "l"(v));
    return r;
}
__device__ __forceinline__ ull dup2(float x) {
    ull d;
    asm("mov.b64 %0, {%1, %1};" : "=l"(d) : "f"(x));
    return d;
}

// ---------------------------------------------------------------------------
// Fused kernel: dual MLP (8->64->64->1) + quadrature + MIMICS epilogue.
// 512 blocks x 128 threads, 16 samples/block.
// SAMPLE-PACKED FFMA2 (the 14.8us dataflow): thread owns 1 column (c=t&63),
// 8 samples (4 packed pairs) for BOTH MLPs = 8 FFMA2 chains. Activations in
// [col][sample] smem rows -> broadcast LDS.128 (1 wavefront); weights are
// warp-coalesced LDG.32 (1 wavefront) duplicated with 1 ALU mov.
// NEW: explicit software pipeline in the K=64 loop — activations prefetched
// at distance 1 (covers LDS 29cyc), weights at distance 2 (covers LDG ~39cyc).
// 128x32 orientation quadrature collapsed analytically to 3 theta moments
// (exact: uniform 32-pt phi-sum of cos^k, k<=4, equals continuous mean).
// ---------------------------------------------------------------------------
__global__ __launch_bounds__(NTHR)
void pinn_kernel(const float* __restrict__ X,
                 const float* __restrict__ theta,
                 const float* __restrict__ Wp1, const float* __restrict__ bp1,
                 const float* __restrict__ Wp2, const float* __restrict__ bp2,
                 const float* __restrict__ Wp3, const float* __restrict__ bp3,
                 const float* __restrict__ Wc1, const float* __restrict__ bc1,
                 const float* __restrict__ Wc2, const float* __restrict__ bc2,
                 const float* __restrict__ Wc3, const float* __restrict__ bc3,
                 const float* __restrict__ nb_raw, const float* __restrict__ nl_raw,
                 const float* __restrict__ so_raw, const float* __restrict__ mg_raw,
                 const float* __restrict__ s_raw,
                 float* __restrict__ out) {
    __shared__ float XT [NF ][PIT];                  // [feature][sample]
    __shared__ float H1p[HID][PIT], H1c[HID][PIT];   // [col][sample]
    __shared__ float H2p[HID][PIT], H2c[HID][PIT];
    __shared__ float qs[4][NTHR];
    __shared__ float qsum[4];
    __shared__ float Ys[2][TILE];

    const int t = threadIdx.x;
    const int base = blockIdx.x * TILE;
    const float PI = 3.14159265358979f;

    // ---- prefetch epilogue scalars + theta EARLY ----
    float pf_nb = 0.f, pf_nl = 0.f, pf_mg = 0.f, pf_s = 0.f, pf_th = 0.f;
    if (t < TILE) {
        pf_nb = nb_raw[0]; pf_nl = nl_raw[0];
        pf_mg = mg_raw[0]; pf_s  = s_raw[0];
        pf_th = theta[base + t];
    }

    // ---- stage: quadrature point per thread + X [feature][sample] ----
    {
        float sig_o = (10.0f + 70.0f * sigm(so_raw[0])) * (PI / 180.0f);
        float th  = (float)t * (PI * 0.5f / 127.0f);   // linspace(0, pi/2, 128)
        float d   = th - PI * 0.25f;
        float pdf = expf(-d * d / (2.0f * sig_o * sig_o)) * sinf(th);
        float c = cosf(th), s = sinf(th);
        float c2 = c * c, s2 = s * s;
        qs[0][t] = pdf;
        qs[1][t] = pdf * c2 * c2;
        qs[2][t] = pdf * c2 * s2;
        qs[3][t] = pdf * s2 * s2;

        int r = t >> 3, k = t & 7;                     // 16*8 = 128 values
        XT[k][r] = X[base * NF + t];
    }
    __syncthreads();

    // lane geometry: 1 column, 8 samples (4 packed pairs)
    const int c   = t & 63;          // hidden column owned
    const int sg8 = (t >> 6) * 8;    // first sample owned

    ull ap0, ap1, ap2, ap3, ac0, ac1, ac2, ac3;   // packed (s,s+1) accs

    // ================= layer 1 (both MLPs): K = 8 =================
    {
        ull bp = dup2(__ldg(bp1 + c));
        ull bc = dup2(__ldg(bc1 + c));
        ap0 = bp; ap1 = bp; ap2 = bp; ap3 = bp;
        ac0 = bc; ac1 = bc; ac2 = bc; ac3 = bc;
        #pragma unroll
        for (int k = 0; k < NF; k++) {
            ulonglong2 A0 = *(const ulonglong2*)&XT[k][sg8];       // pairs 0,1
            ulonglong2 A1 = *(const ulonglong2*)&XT[k][sg8 + 4];   // pairs 2,3
            ull wp = dup2(__ldg(Wp1 + k * HID + c));
            ull wc = dup2(__ldg(Wc1 + k * HID + c));
            ap0 = fma2(A0.x, wp, ap0); ap1 = fma2(A0.y, wp, ap1);
            ap2 = fma2(A1.x, wp, ap2); ap3 = fma2(A1.y, wp, ap3);
            ac0 = fma2(A0.x, wc, ac0); ac1 = fma2(A0.y, wc, ac1);
            ac2 = fma2(A1.x, wc, ac2); ac3 = fma2(A1.y, wc, ac3);
        }
        float2 u;
        u = unpack2(ap0); *(float2*)&H1p[c][sg8 + 0] = make_float2(tanha(u.x), tanha(u.y));
        u = unpack2(ap1); *(float2*)&H1p[c][sg8 + 2] = make_float2(tanha(u.x), tanha(u.y));
        u = unpack2(ap2); *(float2*)&H1p[c][sg8 + 4] = make_float2(tanha(u.x), tanha(u.y));
        u = unpack2(ap3); *(float2*)&H1p[c][sg8 + 6] = make_float2(tanha(u.x), tanha(u.y));
        u = unpack2(ac0); *(float2*)&H1c[c][sg8 + 0] = make_float2(tanha(u.x), tanha(u.y));
        u = unpack2(ac1); *(float2*)&H1c[c][sg8 + 2] = make_float2(tanha(u.x), tanha(u.y));
        u = unpack2(ac2); *(float2*)&H1c[c][sg8 + 4] = make_float2(tanha(u.x), tanha(u.y));
        u = unpack2(ac3); *(float2*)&H1c[c][sg8 + 6] = make_float2(tanha(u.x), tanha(u.y));
    }
    __syncthreads();

    // ========== layer 2 (both MLPs): K = 64, software-pipelined ==========
    {
        ull bp = dup2(__ldg(bp2 + c));
        ull bc = dup2(__ldg(bc2 + c));
        ap0 = bp; ap1 = bp; ap2 = bp; ap3 = bp;
        ac0 = bc; ac1 = bc; ac2 = bc; ac3 = bc;

        // weight prefetch pipeline, distance 2
        float wpb0 = __ldg(Wp2 + c);
        float wcb0 = __ldg(Wc2 + c);
        float wpb1 = __ldg(Wp2 + HID + c);
        float wcb1 = __ldg(Wc2 + HID + c);
        // activation prefetch, distance 1
        ulonglong2 nAp0 = *(const ulonglong2*)&H1p[0][sg8];
        ulonglong2 nAp1 = *(const ulonglong2*)&H1p[0][sg8 + 4];
        ulonglong2 nAc0 = *(const ulonglong2*)&H1c[0][sg8];
        ulonglong2 nAc1 = *(const ulonglong2*)&H1c[0][sg8 + 4];

        #pragma unroll 8
        for (int k = 0; k < HID; k++) {
            ull wp = dup2(wpb0), wc = dup2(wcb0);
            wpb0 = wpb1; wcb0 = wcb1;
            if (k + 2 < HID) {
                wpb1 = __ldg(Wp2 + (k + 2) * HID + c);
                wcb1 = __ldg(Wc2 + (k + 2) * HID + c);
            }
            ulonglong2 Ap0 = nAp0, Ap1 = nAp1, Ac0 = nAc0, Ac1 = nAc1;
            if (k + 1 < HID) {
                nAp0 = *(const ulonglong2*)&H1p[k + 1][sg8];
                nAp1 = *(const ulonglong2*)&H1p[k + 1][sg8 + 4];
                nAc0 = *(const ulonglong2*)&H1c[k + 1][sg8];
                nAc1 = *(const ulonglong2*)&H1c[k + 1][sg8 + 4];
            }
            ap0 = fma2(Ap0.x, wp, ap0); ap1 = fma2(Ap0.y, wp, ap1);
            ap2 = fma2(Ap1.x, wp, ap2); ap3 = fma2(Ap1.y, wp, ap3);
            ac0 = fma2(Ac0.x, wc, ac0); ac1 = fma2(Ac0.y, wc, ac1);
            ac2 = fma2(Ac1.x, wc, ac2); ac3 = fma2(Ac1.y, wc, ac3);
        }
        // H2 is a separate buffer: no hazard with pending H1 reads
        float2 u;
        u = unpack2(ap0); *(float2*)&H2p[c][sg8 + 0] = make_float2(tanha(u.x), tanha(u.y));
        u = unpack2(ap1); *(float2*)&H2p[c][sg8 + 2] = make_float2(tanha(u.x), tanha(u.y));
        u = unpack2(ap2); *(float2*)&H2p[c][sg8 + 4] = make_float2(tanha(u.x), tanha(u.y));
        u = unpack2(ap3); *(float2*)&H2p[c][sg8 + 6] = make_float2(tanha(u.x), tanha(u.y));
        u = unpack2(ac0); *(float2*)&H2c[c][sg8 + 0] = make_float2(tanha(u.x), tanha(u.y));
        u = unpack2(ac1); *(float2*)&H2c[c][sg8 + 2] = make_float2(tanha(u.x), tanha(u.y));
        u = unpack2(ac2); *(float2*)&H2c[c][sg8 + 4] = make_float2(tanha(u.x), tanha(u.y));
        u = unpack2(ac3); *(float2*)&H2c[c][sg8 + 6] = make_float2(tanha(u.x), tanha(u.y));
    }
    __syncthreads();

    // ---- parallel: warps 0-1 reduce quadrature; warp 2 does layer 3 ----
    {
        int w = t >> 5, lane = t & 31;
        if (w < 2) {
            #pragma unroll
            for (int a = 2 * w; a < 2 * w + 2; a++) {
                float v = qs[a][lane] + qs[a][lane + 32]
                        + qs[a][lane + 64] + qs[a][lane + 96];
                v += __shfl_xor_sync(0xFFFFFFFF, v, 16);
                v += __shfl_xor_sync(0xFFFFFFFF, v, 8);
                v += __shfl_xor_sync(0xFFFFFFFF, v, 4);
                v += __shfl_xor_sync(0xFFFFFFFF, v, 2);
                v += __shfl_xor_sync(0xFFFFFFFF, v, 1);
                if (lane == 0) qsum[a] = v;
            }
        } else if (w == 2) {
            int idx = t - 64;                  // 0..31
            int mlp = idx >> 4, rr = idx & 15; // 2 MLPs x 16 samples
            const float* W3 = mlp ? Wc3 : Wp3;
            const float* H2 = mlp ? &H2c[0][0] : &H2p[0][0];
            float v0 = __ldg(mlp ? bc3 : bp3);
            float v1 = 0.f, v2 = 0.f, v3 = 0.f;
            #pragma unroll 4
            for (int k = 0; k < HID; k += 4) {  // k = column index here
                v0 = fmaf(H2[(k + 0) * PIT + rr], __ldg(W3 + k + 0), v0);
                v1 = fmaf(H2[(k + 1) * PIT + rr], __ldg(W3 + k + 1), v1);
                v2 = fmaf(H2[(k + 2) * PIT + rr], __ldg(W3 + k + 2), v2);
                v3 = fmaf(H2[(k + 3) * PIT + rr], __ldg(W3 + k + 3), v3);
            }
            Ys[mlp][rr] = (v0 + v1) + (v2 + v3);
        }
    }
    __syncthreads();

    // ---- epilogue: MIMICS physics, analytically reduced quadrature ----
    if (t < TILE) {
        int s = base + t;

        float inv = 1.0f / qsum[0];
        float S1 = qsum[1] * inv, S2 = qsum[2] * inv, S3 = qsum[3] * inv;

        float Nb = exp10f(2.0f + 3.0f * sigm(pf_nb));
        float Nl = exp10f(3.0f + 3.0f * sigm(pf_nl));
        float dens = Nb * 1e-4f + Nl * 1e-6f;

        float mg   = 0.05f + 0.75f * sigm(pf_mg);
        float epsv = 1.5f + 20.0f * mg;
        float Kv   = (epsv - 1.0f) / (epsv + 2.0f);
        float Kv2  = Kv * Kv;

        float sm = 0.01f * (0.5f + 5.5f * sigm(pf_s));
        float kw = 2.0f * PI * (5.405e9f / 2.998e8f);
        float tt = 2.0f * kw * sm;
        float c_r = tt * tt;

        float m_v   = 0.93f * sigm(Ys[0][t]);
        float delta = 0.05f * tanh_acc(Ys[1][t]);   // direct output: exact tanh
        float eps_g = 3.0f + 25.0f * m_v + 10.0f * m_v * m_v;

        float ti = pf_th * (PI / 180.0f);
        float ct = cosf(ti), st = sinf(ti);
        float ct2 = ct * ct, st2 = st * st;

        float crown_vv = Kv2 * (ct2 * ct2 * S1 + 3.0f * ct2 * st2 * S2
                                + 0.375f * st2 * st2 * S3);
        float crown_vh = Kv2 * (0.5f * ct2 * S2 + 0.125f * st2 * S3);

        float root  = sqrtf(eps_g - st2);
        float r_v   = (eps_g * ct - root) / (eps_g * ct + root);
        float gamma = r_v * r_v;
        float rough = expf(-c_r * ct2);
        float ground = gamma * rough * ct2;

        float svv = dens * crown_vv + ground;
        float svh = dens * crown_vh + 0.05f * ground;

        out[0 * N_TOT + s] = m_v;
        out[1 * N_TOT + s] = delta;
        out[2 * N_TOT + s] = m_v + delta;
        out[3 * N_TOT + s] = 10.0f * log10f(svv + 1e-12f);
        out[4 * N_TOT + s] = 10.0f * log10f(svh + 1e-12f);
        out[5 * N_TOT + s] = eps_g;
    }
}

extern "C" void kernel_launch(void* const* d_in, const int* in_sizes, int n_in,
                              void* d_out, int out_size) {
    // inputs: 0 X, 1 theta_inc_deg, 2 vv_db_observed (unused),
    // 3 Wp1, 4 bp1, 5 Wp2, 6 bp2, 7 Wp3, 8 bp3,
    // 9 Wc1, 10 bc1, 11 Wc2, 12 bc2, 13 Wc3, 14 bc3,
    // 15 nb_raw, 16 nl_raw, 17 so_raw, 18 mg_raw, 19 s_raw
    (void)in_sizes; (void)n_in; (void)out_size;

    pinn_kernel<<<NBLK, NTHR>>>(
        (const float*)d_in[0], (const float*)d_in[1],
        (const float*)d_in[3], (const float*)d_in[4],
        (const float*)d_in[5], (const float*)d_in[6],
        (const float*)d_in[7], (const float*)d_in[8],
        (const float*)d_in[9], (const float*)d_in[10],
        (const float*)d_in[11], (const float*)d_in[12],
        (const float*)d_in[13], (const float*)d_in[14],
        (const float*)d_in[15], (const float*)d_in[16],
        (const float*)d_in[17], (const float*)d_in[18],
        (const float*)d_in[19],
        (float*)d_out);
}

// round 9
// speedup vs baseline: 1.0194x; 1.0194x over previous
#include <cuda_runtime.h>
#include <math.h>

#define N_TOT  8192
#define NF     8
#define HID    64
#define TILE   8
#define NTHR   64
#define NBLK   (N_TOT / TILE)   // 1024
#define PIT    12               // smem row pitch (floats): 8 samples + pad, 16B-aligned

typedef unsigned long long ull;

__device__ __forceinline__ float sigm(float x) {
    return 1.0f / (1.0f + __expf(-x));
}

// Accurate tanh (only where it feeds an output directly).
__device__ __forceinline__ float tanh_acc(float x) {
    float ax = fabsf(x);
    if (ax < 0.0625f) {
        float x2 = x * x;
        return x * (1.0f + x2 * (-0.33333333f + x2 * 0.13333334f));
    }
    float e = __expf(-2.0f * ax);
    float r = (1.0f - e) / (1.0f + e);
    return (x < 0.0f) ? -r : r;
}

// HW tanh approximation (MUFU.TANH) for hidden layers.
__device__ __forceinline__ float tanha(float x) {
    float r;
    asm("tanh.approx.f32 %0, %1;" : "=f"(r) : "f"(x));
    return r;
}

// Packed dual-lane FMA (sm_103a FFMA2; ptxas never emits from C++).
__device__ __forceinline__ ull fma2(ull a, ull b, ull c) {
    ull d;
    asm("fma.rn.f32x2 %0, %1, %2, %3;" : "=l"(d) : "l"(a), "l"(b), "l"(c));
    return d;
}
__device__ __forceinline__ float2 unpack2(ull v) {
    float2 r;
    asm("mov.b64 {%0, %1}, %2;" : "=f"(r.x), "=f"(r.y) : "l"(v));
    return r;
}
__device__ __forceinline__ ull dup2(float x) {
    ull d;
    asm("mov.b64 %0, {%1, %1};" : "=l"(d) : "f"(x));
    return d;
}

// ---------------------------------------------------------------------------
// Fused kernel: dual MLP (8->64->64->1) + quadrature + MIMICS epilogue.
// 1024 blocks x 64 threads (2 warps), 8 samples/block.
// Per-thread dataflow identical to the proven 14.8us kernel: 1 column (c=t),
// 8 samples (4 packed FFMA2 pairs) for BOTH MLPs = 8 chains; activations in
// [col][sample] smem rows -> broadcast LDS.128 (1 wavefront); weights are
// warp-coalesced LDG.32 duplicated with 1 ALU mov; explicit software pipeline
// (activations prefetched at distance 1, weights at distance 2).
// NEW vs R8: granularity. 2-warp blocks make barriers ~7cyc and give ~7
// independent blocks/SM to fill latency holes (same total warps + traffic).
// 128x32 orientation quadrature collapsed analytically to 3 theta moments
// (exact: uniform 32-pt phi-sum of cos^k, k<=4, equals continuous mean).
// ---------------------------------------------------------------------------
__global__ __launch_bounds__(NTHR)
void pinn_kernel(const float* __restrict__ X,
                 const float* __restrict__ theta,
                 const float* __restrict__ Wp1, const float* __restrict__ bp1,
                 const float* __restrict__ Wp2, const float* __restrict__ bp2,
                 const float* __restrict__ Wp3, const float* __restrict__ bp3,
                 const float* __restrict__ Wc1, const float* __restrict__ bc1,
                 const float* __restrict__ Wc2, const float* __restrict__ bc2,
                 const float* __restrict__ Wc3, const float* __restrict__ bc3,
                 const float* __restrict__ nb_raw, const float* __restrict__ nl_raw,
                 const float* __restrict__ so_raw, const float* __restrict__ mg_raw,
                 const float* __restrict__ s_raw,
                 float* __restrict__ out) {
    __shared__ float XT [NF ][PIT];                  // [feature][sample]
    __shared__ float H1p[HID][PIT], H1c[HID][PIT];   // [col][sample]
    __shared__ float H2p[HID][PIT], H2c[HID][PIT];
    __shared__ float qs[4][128];
    __shared__ float qsum[4];
    __shared__ float Ys[2][TILE];

    const int t = threadIdx.x;
    const int base = blockIdx.x * TILE;
    const float PI = 3.14159265358979f;

    // ---- prefetch epilogue scalars + theta EARLY ----
    float pf_nb = 0.f, pf_nl = 0.f, pf_mg = 0.f, pf_s = 0.f, pf_th = 0.f;
    if (t < TILE) {
        pf_nb = nb_raw[0]; pf_nl = nl_raw[0];
        pf_mg = mg_raw[0]; pf_s  = s_raw[0];
        pf_th = theta[base + t];
    }

    // ---- stage: 2 quadrature points per thread + X [feature][sample] ----
    {
        float sig_o = (10.0f + 70.0f * sigm(so_raw[0])) * (PI / 180.0f);
        float inv2s2 = 1.0f / (2.0f * sig_o * sig_o);
        #pragma unroll
        for (int i = t; i < 128; i += NTHR) {
            float th  = (float)i * (PI * 0.5f / 127.0f);  // linspace(0,pi/2,128)
            float d   = th - PI * 0.25f;
            float pdf = expf(-d * d * inv2s2) * sinf(th);
            float c = cosf(th), s = sinf(th);
            float c2 = c * c, s2 = s * s;
            qs[0][i] = pdf;
            qs[1][i] = pdf * c2 * c2;
            qs[2][i] = pdf * c2 * s2;
            qs[3][i] = pdf * s2 * s2;
        }
        int r = t >> 3, k = t & 7;                        // 8*8 = 64 values
        XT[k][r] = X[base * NF + t];
    }
    __syncthreads();

    // lane geometry: 1 column (c = t), samples 0..7 (4 packed pairs)
    const int c = t;

    ull ap0, ap1, ap2, ap3, ac0, ac1, ac2, ac3;   // packed (s,s+1) accs

    // ================= layer 1 (both MLPs): K = 8 =================
    {
        ull bp = dup2(__ldg(bp1 + c));
        ull bc = dup2(__ldg(bc1 + c));
        ap0 = bp; ap1 = bp; ap2 = bp; ap3 = bp;
        ac0 = bc; ac1 = bc; ac2 = bc; ac3 = bc;
        #pragma unroll
        for (int k = 0; k < NF; k++) {
            ulonglong2 A0 = *(const ulonglong2*)&XT[k][0];   // pairs 0,1
            ulonglong2 A1 = *(const ulonglong2*)&XT[k][4];   // pairs 2,3
            ull wp = dup2(__ldg(Wp1 + k * HID + c));
            ull wc = dup2(__ldg(Wc1 + k * HID + c));
            ap0 = fma2(A0.x, wp, ap0); ap1 = fma2(A0.y, wp, ap1);
            ap2 = fma2(A1.x, wp, ap2); ap3 = fma2(A1.y, wp, ap3);
            ac0 = fma2(A0.x, wc, ac0); ac1 = fma2(A0.y, wc, ac1);
            ac2 = fma2(A1.x, wc, ac2); ac3 = fma2(A1.y, wc, ac3);
        }
        float2 u;
        u = unpack2(ap0); *(float2*)&H1p[c][0] = make_float2(tanha(u.x), tanha(u.y));
        u = unpack2(ap1); *(float2*)&H1p[c][2] = make_float2(tanha(u.x), tanha(u.y));
        u = unpack2(ap2); *(float2*)&H1p[c][4] = make_float2(tanha(u.x), tanha(u.y));
        u = unpack2(ap3); *(float2*)&H1p[c][6] = make_float2(tanha(u.x), tanha(u.y));
        u = unpack2(ac0); *(float2*)&H1c[c][0] = make_float2(tanha(u.x), tanha(u.y));
        u = unpack2(ac1); *(float2*)&H1c[c][2] = make_float2(tanha(u.x), tanha(u.y));
        u = unpack2(ac2); *(float2*)&H1c[c][4] = make_float2(tanha(u.x), tanha(u.y));
        u = unpack2(ac3); *(float2*)&H1c[c][6] = make_float2(tanha(u.x), tanha(u.y));
    }
    __syncthreads();

    // ========== layer 2 (both MLPs): K = 64, software-pipelined ==========
    {
        ull bp = dup2(__ldg(bp2 + c));
        ull bc = dup2(__ldg(bc2 + c));
        ap0 = bp; ap1 = bp; ap2 = bp; ap3 = bp;
        ac0 = bc; ac1 = bc; ac2 = bc; ac3 = bc;

        // weight prefetch pipeline, distance 2
        float wpb0 = __ldg(Wp2 + c);
        float wcb0 = __ldg(Wc2 + c);
        float wpb1 = __ldg(Wp2 + HID + c);
        float wcb1 = __ldg(Wc2 + HID + c);
        // activation prefetch, distance 1
        ulonglong2 nAp0 = *(const ulonglong2*)&H1p[0][0];
        ulonglong2 nAp1 = *(const ulonglong2*)&H1p[0][4];
        ulonglong2 nAc0 = *(const ulonglong2*)&H1c[0][0];
        ulonglong2 nAc1 = *(const ulonglong2*)&H1c[0][4];

        #pragma unroll 8
        for (int k = 0; k < HID; k++) {
            ull wp = dup2(wpb0), wc = dup2(wcb0);
            wpb0 = wpb1; wcb0 = wcb1;
            if (k + 2 < HID) {
                wpb1 = __ldg(Wp2 + (k + 2) * HID + c);
                wcb1 = __ldg(Wc2 + (k + 2) * HID + c);
            }
            ulonglong2 Ap0 = nAp0, Ap1 = nAp1, Ac0 = nAc0, Ac1 = nAc1;
            if (k + 1 < HID) {
                nAp0 = *(const ulonglong2*)&H1p[k + 1][0];
                nAp1 = *(const ulonglong2*)&H1p[k + 1][4];
                nAc0 = *(const ulonglong2*)&H1c[k + 1][0];
                nAc1 = *(const ulonglong2*)&H1c[k + 1][4];
            }
            ap0 = fma2(Ap0.x, wp, ap0); ap1 = fma2(Ap0.y, wp, ap1);
            ap2 = fma2(Ap1.x, wp, ap2); ap3 = fma2(Ap1.y, wp, ap3);
            ac0 = fma2(Ac0.x, wc, ac0); ac1 = fma2(Ac0.y, wc, ac1);
            ac2 = fma2(Ac1.x, wc, ac2); ac3 = fma2(Ac1.y, wc, ac3);
        }
        // H2 is a separate buffer: no hazard with pending H1 reads
        float2 u;
        u = unpack2(ap0); *(float2*)&H2p[c][0] = make_float2(tanha(u.x), tanha(u.y));
        u = unpack2(ap1); *(float2*)&H2p[c][2] = make_float2(tanha(u.x), tanha(u.y));
        u = unpack2(ap2); *(float2*)&H2p[c][4] = make_float2(tanha(u.x), tanha(u.y));
        u = unpack2(ap3); *(float2*)&H2p[c][6] = make_float2(tanha(u.x), tanha(u.y));
        u = unpack2(ac0); *(float2*)&H2c[c][0] = make_float2(tanha(u.x), tanha(u.y));
        u = unpack2(ac1); *(float2*)&H2c[c][2] = make_float2(tanha(u.x), tanha(u.y));
        u = unpack2(ac2); *(float2*)&H2c[c][4] = make_float2(tanha(u.x), tanha(u.y));
        u = unpack2(ac3); *(float2*)&H2c[c][6] = make_float2(tanha(u.x), tanha(u.y));
    }
    __syncthreads();

    // ---- parallel: warp 0 reduces quadrature; warp 1 does layer 3 ----
    {
        int w = t >> 5, lane = t & 31;
        if (w == 0) {
            #pragma unroll
            for (int a = 0; a < 4; a++) {
                float v = qs[a][lane] + qs[a][lane + 32]
                        + qs[a][lane + 64] + qs[a][lane + 96];
                v += __shfl_xor_sync(0xFFFFFFFF, v, 16);
                v += __shfl_xor_sync(0xFFFFFFFF, v, 8);
                v += __shfl_xor_sync(0xFFFFFFFF, v, 4);
                v += __shfl_xor_sync(0xFFFFFFFF, v, 2);
                v += __shfl_xor_sync(0xFFFFFFFF, v, 1);
                if (lane == 0) qsum[a] = v;
            }
        } else {
            // 16 dot-products (2 MLPs x 8 samples), 2 lanes per dot
            int d    = lane >> 1;          // 0..15
            int half = lane & 1;
            int mlp  = d >> 3, rr = d & 7;
            const float* W3 = mlp ? Wc3 : Wp3;
            const float* H2 = mlp ? &H2c[0][0] : &H2p[0][0];
            float v0 = half ? 0.f : __ldg(mlp ? bc3 : bp3);
            float v1 = 0.f;
            #pragma unroll 8
            for (int j = 0; j < 32; j += 2) {
                int k0 = 2 * j + half;          // even j -> chain 0
                int k1 = 2 * (j + 1) + half;    // odd  j -> chain 1
                v0 = fmaf(H2[k0 * PIT + rr], __ldg(W3 + k0), v0);
                v1 = fmaf(H2[k1 * PIT + rr], __ldg(W3 + k1), v1);
            }
            float v = v0 + v1;
            v += __shfl_xor_sync(0xFFFFFFFF, v, 1);
            if (half == 0) Ys[mlp][rr] = v;
        }
    }
    __syncthreads();

    // ---- epilogue: MIMICS physics, analytically reduced quadrature ----
    if (t < TILE) {
        int s = base + t;

        float inv = 1.0f / qsum[0];
        float S1 = qsum[1] * inv, S2 = qsum[2] * inv, S3 = qsum[3] * inv;

        float Nb = exp10f(2.0f + 3.0f * sigm(pf_nb));
        float Nl = exp10f(3.0f + 3.0f * sigm(pf_nl));
        float dens = Nb * 1e-4f + Nl * 1e-6f;

        float mg   = 0.05f + 0.75f * sigm(pf_mg);
        float epsv = 1.5f + 20.0f * mg;
        float Kv   = (epsv - 1.0f) / (epsv + 2.0f);
        float Kv2  = Kv * Kv;

        float sm = 0.01f * (0.5f + 5.5f * sigm(pf_s));
        float kw = 2.0f * PI * (5.405e9f / 2.998e8f);
        float tt = 2.0f * kw * sm;
        float c_r = tt * tt;

        float m_v   = 0.93f * sigm(Ys[0][t]);
        float delta = 0.05f * tanh_acc(Ys[1][t]);   // direct output: exact tanh
        float eps_g = 3.0f + 25.0f * m_v + 10.0f * m_v * m_v;

        float ti = pf_th * (PI / 180.0f);
        float ct = cosf(ti), st = sinf(ti);
        float ct2 = ct * ct, st2 = st * st;

        float crown_vv = Kv2 * (ct2 * ct2 * S1 + 3.0f * ct2 * st2 * S2
                                + 0.375f * st2 * st2 * S3);
        float crown_vh = Kv2 * (0.5f * ct2 * S2 + 0.125f * st2 * S3);

        float root  = sqrtf(eps_g - st2);
        float r_v   = (eps_g * ct - root) / (eps_g * ct + root);
        float gamma = r_v * r_v;
        float rough = expf(-c_r * ct2);
        float ground = gamma * rough * ct2;

        float svv = dens * crown_vv + ground;
        float svh = dens * crown_vh + 0.05f * ground;

        out[0 * N_TOT + s] = m_v;
        out[1 * N_TOT + s] = delta;
        out[2 * N_TOT + s] = m_v + delta;
        out[3 * N_TOT + s] = 10.0f * log10f(svv + 1e-12f);
        out[4 * N_TOT + s] = 10.0f * log10f(svh + 1e-12f);
        out[5 * N_TOT + s] = eps_g;
    }
}

extern "C" void kernel_launch(void* const* d_in, const int* in_sizes, int n_in,
                              void* d_out, int out_size) {
    // inputs: 0 X, 1 theta_inc_deg, 2 vv_db_observed (unused),
    // 3 Wp1, 4 bp1, 5 Wp2, 6 bp2, 7 Wp3, 8 bp3,
    // 9 Wc1, 10 bc1, 11 Wc2, 12 bc2, 13 Wc3, 14 bc3,
    // 15 nb_raw, 16 nl_raw, 17 so_raw, 18 mg_raw, 19 s_raw
    (void)in_sizes; (void)n_in; (void)out_size;

    pinn_kernel<<<NBLK, NTHR>>>(
        (const float*)d_in[0], (const float*)d_in[1],
        (const float*)d_in[3], (const float*)d_in[4],
        (const float*)d_in[5], (const float*)d_in[6],
        (const float*)d_in[7], (const float*)d_in[8],
        (const float*)d_in[9], (const float*)d_in[10],
        (const float*)d_in[11], (const float*)d_in[12],
        (const float*)d_in[13], (const float*)d_in[14],
        (const float*)d_in[15], (const float*)d_in[16],
        (const float*)d_in[17], (const float*)d_in[18],
        (const float*)d_in[19],
        (float*)d_out);
}

// round 10
// speedup vs baseline: 1.1569x; 1.1348x over previous
#include <cuda_runtime.h>
#include <math.h>

#define N_TOT  8192
#define NF     8
#define HID    64
#define TILE   8
#define NTHR   32
#define NBLK   (N_TOT / TILE)   // 1024
#define PIT    12               // smem row pitch (floats): 8 samples + pad, 16B-aligned

typedef unsigned long long ull;

__device__ __forceinline__ float sigm(float x) {
    return 1.0f / (1.0f + __expf(-x));
}

// Accurate tanh (only where it feeds an output directly).
__device__ __forceinline__ float tanh_acc(float x) {
    float ax = fabsf(x);
    if (ax < 0.0625f) {
        float x2 = x * x;
        return x * (1.0f + x2 * (-0.33333333f + x2 * 0.13333334f));
    }
    float e = __expf(-2.0f * ax);
    float r = (1.0f - e) / (1.0f + e);
    return (x < 0.0f) ? -r : r;
}

// HW tanh approximation (MUFU.TANH) for hidden layers.
__device__ __forceinline__ float tanha(float x) {
    float r;
    asm("tanh.approx.f32 %0, %1;" : "=f"(r) : "f"(x));
    return r;
}

// Packed dual-lane FMA (sm_103a FFMA2; ptxas never emits from C++).
__device__ __forceinline__ ull fma2(ull a, ull b, ull c) {
    ull d;
    asm("fma.rn.f32x2 %0, %1, %2, %3;" : "=l"(d) : "l"(a), "l"(b), "l"(c));
    return d;
}
__device__ __forceinline__ float2 unpack2(ull v) {
    float2 r;
    asm("mov.b64 {%0, %1}, %2;" : "=f"(r.x), "=f"(r.y) : "l"(v));
    return r;
}
__device__ __forceinline__ ull dup2(float x) {
    ull d;
    asm("mov.b64 %0, {%1, %1};" : "=l"(d) : "f"(x));
    return d;
}

// tanh 8 packed values -> one smem row of 8 floats
__device__ __forceinline__ void tanh_store8(float* row, ull a0, ull a1, ull a2, ull a3) {
    float2 u;
    u = unpack2(a0); *(float2*)&row[0] = make_float2(tanha(u.x), tanha(u.y));
    u = unpack2(a1); *(float2*)&row[2] = make_float2(tanha(u.x), tanha(u.y));
    u = unpack2(a2); *(float2*)&row[4] = make_float2(tanha(u.x), tanha(u.y));
    u = unpack2(a3); *(float2*)&row[6] = make_float2(tanha(u.x), tanha(u.y));
}

// ---------------------------------------------------------------------------
// Fused kernel: dual MLP (8->64->64->1) + quadrature + MIMICS epilogue.
// 1024 blocks x 32 threads (ONE warp per block): all sync is __syncwarp(),
// zero bar.sync. Thread owns 2 adjacent columns (c2=2t) x 8 samples
// (4 packed pairs) x 2 MLPs = 16 FFMA2 chains. Per k-iter: 4 broadcast
// LDS.128 + 2 coalesced LDG.64 + 4 dup movs + 16 FFMA2 -> 62% FMA slots.
// Software pipeline: weights prefetched at distance 2, activations at 1.
// 128x32 orientation quadrature collapsed analytically to 3 theta moments
// (exact: uniform 32-pt phi-sum of cos^k, k<=4, equals continuous mean).
// ---------------------------------------------------------------------------
__global__ __launch_bounds__(NTHR)
void pinn_kernel(const float* __restrict__ X,
                 const float* __restrict__ theta,
                 const float* __restrict__ Wp1, const float* __restrict__ bp1,
                 const float* __restrict__ Wp2, const float* __restrict__ bp2,
                 const float* __restrict__ Wp3, const float* __restrict__ bp3,
                 const float* __restrict__ Wc1, const float* __restrict__ bc1,
                 const float* __restrict__ Wc2, const float* __restrict__ bc2,
                 const float* __restrict__ Wc3, const float* __restrict__ bc3,
                 const float* __restrict__ nb_raw, const float* __restrict__ nl_raw,
                 const float* __restrict__ so_raw, const float* __restrict__ mg_raw,
                 const float* __restrict__ s_raw,
                 float* __restrict__ out) {
    __shared__ float XT [NF ][PIT];                  // [feature][sample]
    __shared__ float H1p[HID][PIT], H1c[HID][PIT];   // [col][sample]
    __shared__ float H2p[HID][PIT], H2c[HID][PIT];
    __shared__ float qs[4][128];
    __shared__ float qsum[4];
    __shared__ float Ys[2][TILE];

    const int t = threadIdx.x;          // 0..31
    const int base = blockIdx.x * TILE;
    const float PI = 3.14159265358979f;

    // ---- prefetch epilogue scalars + theta EARLY ----
    float pf_nb = 0.f, pf_nl = 0.f, pf_mg = 0.f, pf_s = 0.f, pf_th = 0.f;
    if (t < TILE) {
        pf_nb = nb_raw[0]; pf_nl = nl_raw[0];
        pf_mg = mg_raw[0]; pf_s  = s_raw[0];
        pf_th = theta[base + t];
    }

    // ---- stage: 4 quadrature points per thread + X (2 values/thread) ----
    {
        float sig_o = (10.0f + 70.0f * sigm(so_raw[0])) * (PI / 180.0f);
        float inv2s2 = 1.0f / (2.0f * sig_o * sig_o);
        #pragma unroll
        for (int i = t; i < 128; i += NTHR) {
            float th  = (float)i * (PI * 0.5f / 127.0f);  // linspace(0,pi/2,128)
            float d   = th - PI * 0.25f;
            float pdf = expf(-d * d * inv2s2) * sinf(th);
            float c = cosf(th), s = sinf(th);
            float c2 = c * c, s2 = s * s;
            qs[0][i] = pdf;
            qs[1][i] = pdf * c2 * c2;
            qs[2][i] = pdf * c2 * s2;
            qs[3][i] = pdf * s2 * s2;
        }
        #pragma unroll
        for (int idx = t; idx < TILE * NF; idx += NTHR) {
            int r = idx >> 3, k = idx & 7;
            XT[k][r] = X[base * NF + idx];
        }
    }
    __syncwarp();

    // lane geometry: 2 adjacent columns, samples 0..7 (4 packed pairs)
    const int c2 = 2 * t;

    // accumulators: a{p|c}{col}{pair}
    ull ap00, ap01, ap02, ap03, ap10, ap11, ap12, ap13;
    ull ac00, ac01, ac02, ac03, ac10, ac11, ac12, ac13;

    // ================= layer 1 (both MLPs): K = 8 =================
    {
        float2 bp = __ldg((const float2*)(bp1 + c2));
        float2 bc = __ldg((const float2*)(bc1 + c2));
        ull b;
        b = dup2(bp.x); ap00 = b; ap01 = b; ap02 = b; ap03 = b;
        b = dup2(bp.y); ap10 = b; ap11 = b; ap12 = b; ap13 = b;
        b = dup2(bc.x); ac00 = b; ac01 = b; ac02 = b; ac03 = b;
        b = dup2(bc.y); ac10 = b; ac11 = b; ac12 = b; ac13 = b;
        #pragma unroll
        for (int k = 0; k < NF; k++) {
            ulonglong2 A0 = *(const ulonglong2*)&XT[k][0];   // pairs 0,1
            ulonglong2 A1 = *(const ulonglong2*)&XT[k][4];   // pairs 2,3
            float2 wpv = __ldg((const float2*)(Wp1 + k * HID + c2));
            float2 wcv = __ldg((const float2*)(Wc1 + k * HID + c2));
            ull wp0 = dup2(wpv.x), wp1 = dup2(wpv.y);
            ull wc0 = dup2(wcv.x), wc1 = dup2(wcv.y);
            ap00 = fma2(A0.x, wp0, ap00); ap01 = fma2(A0.y, wp0, ap01);
            ap02 = fma2(A1.x, wp0, ap02); ap03 = fma2(A1.y, wp0, ap03);
            ap10 = fma2(A0.x, wp1, ap10); ap11 = fma2(A0.y, wp1, ap11);
            ap12 = fma2(A1.x, wp1, ap12); ap13 = fma2(A1.y, wp1, ap13);
            ac00 = fma2(A0.x, wc0, ac00); ac01 = fma2(A0.y, wc0, ac01);
            ac02 = fma2(A1.x, wc0, ac02); ac03 = fma2(A1.y, wc0, ac03);
            ac10 = fma2(A0.x, wc1, ac10); ac11 = fma2(A0.y, wc1, ac11);
            ac12 = fma2(A1.x, wc1, ac12); ac13 = fma2(A1.y, wc1, ac13);
        }
        tanh_store8(&H1p[c2    ][0], ap00, ap01, ap02, ap03);
        tanh_store8(&H1p[c2 + 1][0], ap10, ap11, ap12, ap13);
        tanh_store8(&H1c[c2    ][0], ac00, ac01, ac02, ac03);
        tanh_store8(&H1c[c2 + 1][0], ac10, ac11, ac12, ac13);
    }
    __syncwarp();

    // ========== layer 2 (both MLPs): K = 64, software-pipelined ==========
    {
        float2 bp = __ldg((const float2*)(bp2 + c2));
        float2 bc = __ldg((const float2*)(bc2 + c2));
        ull b;
        b = dup2(bp.x); ap00 = b; ap01 = b; ap02 = b; ap03 = b;
        b = dup2(bp.y); ap10 = b; ap11 = b; ap12 = b; ap13 = b;
        b = dup2(bc.x); ac00 = b; ac01 = b; ac02 = b; ac03 = b;
        b = dup2(bc.y); ac10 = b; ac11 = b; ac12 = b; ac13 = b;

        // weight prefetch pipeline, distance 2
        float2 wpb0 = __ldg((const float2*)(Wp2 + c2));
        float2 wcb0 = __ldg((const float2*)(Wc2 + c2));
        float2 wpb1 = __ldg((const float2*)(Wp2 + HID + c2));
        float2 wcb1 = __ldg((const float2*)(Wc2 + HID + c2));
        // activation prefetch, distance 1
        ulonglong2 nAp0 = *(const ulonglong2*)&H1p[0][0];
        ulonglong2 nAp1 = *(const ulonglong2*)&H1p[0][4];
        ulonglong2 nAc0 = *(const ulonglong2*)&H1c[0][0];
        ulonglong2 nAc1 = *(const ulonglong2*)&H1c[0][4];

        #pragma unroll 8
        for (int k = 0; k < HID; k++) {
            ull wp0 = dup2(wpb0.x), wp1 = dup2(wpb0.y);
            ull wc0 = dup2(wcb0.x), wc1 = dup2(wcb0.y);
            wpb0 = wpb1; wcb0 = wcb1;
            if (k + 2 < HID) {
                wpb1 = __ldg((const float2*)(Wp2 + (k + 2) * HID + c2));
                wcb1 = __ldg((const float2*)(Wc2 + (k + 2) * HID + c2));
            }
            ulonglong2 Ap0 = nAp0, Ap1 = nAp1, Ac0 = nAc0, Ac1 = nAc1;
            if (k + 1 < HID) {
                nAp0 = *(const ulonglong2*)&H1p[k + 1][0];
                nAp1 = *(const ulonglong2*)&H1p[k + 1][4];
                nAc0 = *(const ulonglong2*)&H1c[k + 1][0];
                nAc1 = *(const ulonglong2*)&H1c[k + 1][4];
            }
            ap00 = fma2(Ap0.x, wp0, ap00); ap01 = fma2(Ap0.y, wp0, ap01);
            ap02 = fma2(Ap1.x, wp0, ap02); ap03 = fma2(Ap1.y, wp0, ap03);
            ap10 = fma2(Ap0.x, wp1, ap10); ap11 = fma2(Ap0.y, wp1, ap11);
            ap12 = fma2(Ap1.x, wp1, ap12); ap13 = fma2(Ap1.y, wp1, ap13);
            ac00 = fma2(Ac0.x, wc0, ac00); ac01 = fma2(Ac0.y, wc0, ac01);
            ac02 = fma2(Ac1.x, wc0, ac02); ac03 = fma2(Ac1.y, wc0, ac03);
            ac10 = fma2(Ac0.x, wc1, ac10); ac11 = fma2(Ac0.y, wc1, ac11);
            ac12 = fma2(Ac1.x, wc1, ac12); ac13 = fma2(Ac1.y, wc1, ac13);
        }
        tanh_store8(&H2p[c2    ][0], ap00, ap01, ap02, ap03);
        tanh_store8(&H2p[c2 + 1][0], ap10, ap11, ap12, ap13);
        tanh_store8(&H2c[c2    ][0], ac00, ac01, ac02, ac03);
        tanh_store8(&H2c[c2 + 1][0], ac10, ac11, ac12, ac13);
    }
    __syncwarp();

    // ---- quadrature reduction (whole warp) ----
    {
        #pragma unroll
        for (int a = 0; a < 4; a++) {
            float v = qs[a][t] + qs[a][t + 32] + qs[a][t + 64] + qs[a][t + 96];
            v += __shfl_xor_sync(0xFFFFFFFF, v, 16);
            v += __shfl_xor_sync(0xFFFFFFFF, v, 8);
            v += __shfl_xor_sync(0xFFFFFFFF, v, 4);
            v += __shfl_xor_sync(0xFFFFFFFF, v, 2);
            v += __shfl_xor_sync(0xFFFFFFFF, v, 1);
            if (t == 0) qsum[a] = v;
        }
    }

    // ---- layer 3: 16 dot-products (2 MLPs x 8 samples), 2 lanes per dot ----
    {
        int d    = t >> 1;            // 0..15
        int half = t & 1;
        int mlp  = d >> 3, rr = d & 7;
        const float* W3 = mlp ? Wc3 : Wp3;
        const float* H2 = mlp ? &H2c[0][0] : &H2p[0][0];
        float v0 = half ? 0.f : __ldg(mlp ? bc3 : bp3);
        float v1 = 0.f;
        #pragma unroll 8
        for (int j = 0; j < 32; j += 2) {
            int k0 = 2 * j + half;
            int k1 = 2 * (j + 1) + half;
            v0 = fmaf(H2[k0 * PIT + rr], __ldg(W3 + k0), v0);
            v1 = fmaf(H2[k1 * PIT + rr], __ldg(W3 + k1), v1);
        }
        float v = v0 + v1;
        v += __shfl_xor_sync(0xFFFFFFFF, v, 1);
        if (half == 0) Ys[mlp][rr] = v;
    }
    __syncwarp();

    // ---- epilogue: MIMICS physics, analytically reduced quadrature ----
    if (t < TILE) {
        int s = base + t;

        float inv = 1.0f / qsum[0];
        float S1 = qsum[1] * inv, S2 = qsum[2] * inv, S3 = qsum[3] * inv;

        float Nb = exp10f(2.0f + 3.0f * sigm(pf_nb));
        float Nl = exp10f(3.0f + 3.0f * sigm(pf_nl));
        float dens = Nb * 1e-4f + Nl * 1e-6f;

        float mg   = 0.05f + 0.75f * sigm(pf_mg);
        float epsv = 1.5f + 20.0f * mg;
        float Kv   = (epsv - 1.0f) / (epsv + 2.0f);
        float Kv2  = Kv * Kv;

        float sm = 0.01f * (0.5f + 5.5f * sigm(pf_s));
        float kw = 2.0f * PI * (5.405e9f / 2.998e8f);
        float tt = 2.0f * kw * sm;
        float c_r = tt * tt;

        float m_v   = 0.93f * sigm(Ys[0][t]);
        float delta = 0.05f * tanh_acc(Ys[1][t]);   // direct output: exact tanh
        float eps_g = 3.0f + 25.0f * m_v + 10.0f * m_v * m_v;

        float ti = pf_th * (PI / 180.0f);
        float ct = cosf(ti), st = sinf(ti);
        float ct2 = ct * ct, st2 = st * st;

        float crown_vv = Kv2 * (ct2 * ct2 * S1 + 3.0f * ct2 * st2 * S2
                                + 0.375f * st2 * st2 * S3);
        float crown_vh = Kv2 * (0.5f * ct2 * S2 + 0.125f * st2 * S3);

        float root  = sqrtf(eps_g - st2);
        float r_v   = (eps_g * ct - root) / (eps_g * ct + root);
        float gamma = r_v * r_v;
        float rough = expf(-c_r * ct2);
        float ground = gamma * rough * ct2;

        float svv = dens * crown_vv + ground;
        float svh = dens * crown_vh + 0.05f * ground;

        out[0 * N_TOT + s] = m_v;
        out[1 * N_TOT + s] = delta;
        out[2 * N_TOT + s] = m_v + delta;
        out[3 * N_TOT + s] = 10.0f * log10f(svv + 1e-12f);
        out[4 * N_TOT + s] = 10.0f * log10f(svh + 1e-12f);
        out[5 * N_TOT + s] = eps_g;
    }
}

extern "C" void kernel_launch(void* const* d_in, const int* in_sizes, int n_in,
                              void* d_out, int out_size) {
    // inputs: 0 X, 1 theta_inc_deg, 2 vv_db_observed (unused),
    // 3 Wp1, 4 bp1, 5 Wp2, 6 bp2, 7 Wp3, 8 bp3,
    // 9 Wc1, 10 bc1, 11 Wc2, 12 bc2, 13 Wc3, 14 bc3,
    // 15 nb_raw, 16 nl_raw, 17 so_raw, 18 mg_raw, 19 s_raw
    (void)in_sizes; (void)n_in; (void)out_size;

    pinn_kernel<<<NBLK, NTHR>>>(
        (const float*)d_in[0], (const float*)d_in[1],
        (const float*)d_in[3], (const float*)d_in[4],
        (const float*)d_in[5], (const float*)d_in[6],
        (const float*)d_in[7], (const float*)d_in[8],
        (const float*)d_in[9], (const float*)d_in[10],
        (const float*)d_in[11], (const float*)d_in[12],
        (const float*)d_in[13], (const float*)d_in[14],
        (const float*)d_in[15], (const float*)d_in[16],
        (const float*)d_in[17], (const float*)d_in[18],
        (const float*)d_in[19],
        (float*)d_out);
}